// round 1
// baseline (speedup 1.0000x reference)
#include <cuda_runtime.h>
#include <math.h>

// Problem constants
#define Bb   2
#define Ss   2048
#define Dd   768
#define Hh   12
#define Ii   3072
#define Ll   4
#define HDm  64
#define MTOK (Bb*Ss)          // 4096 tokens
#define D3   (3*Dd)           // 2304

// ---------------- scratch buffers (device globals; no allocation) -----------
__device__ float g_x   [MTOK*Dd];                 // running activation
__device__ float g_h   [MTOK*Dd];                 // LN output
__device__ float g_qkv [MTOK*D3];                 // qkv projections
__device__ float g_logits[(size_t)Bb*Hh*Ss*Ss];  // attention logits (402 MB)
__device__ float g_vals[MTOK*Dd];                 // attn output (pre out-proj)
__device__ float g_ffn [MTOK*Ii];                 // fc1 output

// ---------------- utility: vectorized copy ---------------------------------
__global__ void copy4_kernel(const float4* __restrict__ in, float4* __restrict__ out, int n4) {
    int i = blockIdx.x * blockDim.x + threadIdx.x;
    if (i < n4) out[i] = in[i];
}

// ---------------- LayerNorm: one block per token row (768 cols) -------------
__global__ void ln_kernel(const float* __restrict__ x,
                          const float* __restrict__ w,
                          const float* __restrict__ b,
                          float* __restrict__ out) {
    int row = blockIdx.x;
    const float* xr = x + (size_t)row * Dd;
    float v[3];
    float lsum = 0.f, lsq = 0.f;
#pragma unroll
    for (int i = 0; i < 3; i++) {
        v[i] = xr[threadIdx.x + i * 256];
        lsum += v[i];
        lsq  += v[i] * v[i];
    }
    __shared__ float s1[256], s2[256];
    s1[threadIdx.x] = lsum; s2[threadIdx.x] = lsq;
    __syncthreads();
    for (int off = 128; off > 0; off >>= 1) {
        if (threadIdx.x < off) {
            s1[threadIdx.x] += s1[threadIdx.x + off];
            s2[threadIdx.x] += s2[threadIdx.x + off];
        }
        __syncthreads();
    }
    float mean = s1[0] * (1.f / 768.f);
    float var  = s2[0] * (1.f / 768.f) - mean * mean;
    float inv  = rsqrtf(var + 1e-5f);
#pragma unroll
    for (int i = 0; i < 3; i++) {
        int c = threadIdx.x + i * 256;
        out[(size_t)row * Dd + c] = (v[i] - mean) * inv * w[c] + b[c];
    }
}

// ---------------- generic SGEMM: C = A[MxK] @ B[KxN] + bias (+gelu) (+res) --
// BM=BN=128, BK=8, TM=TN=8, 256 threads. All dims divisible by tile sizes.
template<bool GELU, bool RES>
__global__ void gemm128_kernel(int M, int N, int K,
                               const float* __restrict__ A,
                               const float* __restrict__ Bm,
                               const float* __restrict__ bias,
                               const float* __restrict__ res,
                               float* __restrict__ C) {
    const int BM = 128, BN = 128, BK = 8, TM = 8, TN = 8;
    __shared__ float As[BK][BM];
    __shared__ float Bs[BK][BN];
    int tid  = threadIdx.x;
    int row0 = blockIdx.y * BM, col0 = blockIdx.x * BN;
    int aRow = tid >> 1, aCol = (tid & 1) * 4;
    int bRow = tid >> 5, bCol = (tid & 31) * 4;
    const float* Ag = A  + (size_t)(row0 + aRow) * K + aCol;
    const float* Bg = Bm + (size_t)bRow * N + col0 + bCol;
    int ty = tid >> 4, tx = tid & 15;
    float acc[TM][TN] = {};
    for (int k0 = 0; k0 < K; k0 += BK) {
        float4 a4 = *(const float4*)(Ag + k0);
        As[aCol + 0][aRow] = a4.x;
        As[aCol + 1][aRow] = a4.y;
        As[aCol + 2][aRow] = a4.z;
        As[aCol + 3][aRow] = a4.w;
        float4 b4 = *(const float4*)(Bg + (size_t)k0 * N);
        *(float4*)&Bs[bRow][bCol] = b4;
        __syncthreads();
#pragma unroll
        for (int kk = 0; kk < BK; kk++) {
            float ra[TM], rb[TN];
#pragma unroll
            for (int i = 0; i < TM; i++) ra[i] = As[kk][ty * TM + i];
#pragma unroll
            for (int j = 0; j < TN; j++) rb[j] = Bs[kk][tx * TN + j];
#pragma unroll
            for (int i = 0; i < TM; i++)
#pragma unroll
                for (int j = 0; j < TN; j++) acc[i][j] += ra[i] * rb[j];
        }
        __syncthreads();
    }
#pragma unroll
    for (int i = 0; i < TM; i++) {
        int r = row0 + ty * TM + i;
#pragma unroll
        for (int j = 0; j < TN; j++) {
            int c = col0 + tx * TN + j;
            float v = acc[i][j] + bias[c];
            if (GELU) v = 0.5f * v * (1.0f + erff(v * 0.70710678118654752f));
            if (RES)  v += res[(size_t)r * N + c];
            C[(size_t)r * N + c] = v;
        }
    }
}

// ---------------- attention logits: per (b,h): Q[S,64] @ K[S,64]^T * scale --
__global__ void logits_kernel(const float* __restrict__ qkv,
                              float* __restrict__ logits) {
    const int BM = 128, BN = 128, BK = 8;
    __shared__ float As[BK][BM];
    __shared__ float Bs[BK][BN];
    int tid = threadIdx.x;
    int z = blockIdx.z;
    int b = z / Hh, h = z - b * Hh;
    const float* Qb = qkv + (size_t)b * Ss * D3 + h * 192;
    const float* Kb = Qb + 64;
    int row0 = blockIdx.y * BM, col0 = blockIdx.x * BN;
    int aRow = tid >> 1, aCol = (tid & 1) * 4;
    int bColI = tid >> 1, bD4 = (tid & 1) * 4;
    int ty = tid >> 4, tx = tid & 15;
    float acc[8][8] = {};
    for (int k0 = 0; k0 < HDm; k0 += BK) {
        float4 a4 = *(const float4*)(Qb + (size_t)(row0 + aRow) * D3 + k0 + aCol);
        As[aCol + 0][aRow] = a4.x;
        As[aCol + 1][aRow] = a4.y;
        As[aCol + 2][aRow] = a4.z;
        As[aCol + 3][aRow] = a4.w;
        float4 kv = *(const float4*)(Kb + (size_t)(col0 + bColI) * D3 + k0 + bD4);
        Bs[bD4 + 0][bColI] = kv.x;
        Bs[bD4 + 1][bColI] = kv.y;
        Bs[bD4 + 2][bColI] = kv.z;
        Bs[bD4 + 3][bColI] = kv.w;
        __syncthreads();
#pragma unroll
        for (int kk = 0; kk < BK; kk++) {
            float ra[8], rb[8];
#pragma unroll
            for (int i = 0; i < 8; i++) ra[i] = As[kk][ty * 8 + i];
#pragma unroll
            for (int j = 0; j < 8; j++) rb[j] = Bs[kk][tx * 8 + j];
#pragma unroll
            for (int i = 0; i < 8; i++)
#pragma unroll
                for (int j = 0; j < 8; j++) acc[i][j] += ra[i] * rb[j];
        }
        __syncthreads();
    }
    float* Cb = logits + (size_t)z * Ss * Ss;
#pragma unroll
    for (int i = 0; i < 8; i++) {
        size_t r = row0 + ty * 8 + i;
#pragma unroll
        for (int j = 0; j < 8; j++) {
            Cb[r * Ss + col0 + tx * 8 + j] = acc[i][j] * 0.125f;
        }
    }
}

// ---------------- row softmax over 2048 elements ----------------------------
__global__ void softmax_kernel(float* __restrict__ logits) {
    size_t row = blockIdx.x;
    float* p = logits + row * (size_t)Ss;
    float v[8];
    float m = -1e30f;
#pragma unroll
    for (int i = 0; i < 8; i++) {
        v[i] = p[threadIdx.x + i * 256];
        m = fmaxf(m, v[i]);
    }
    __shared__ float red[256];
    red[threadIdx.x] = m;
    __syncthreads();
    for (int off = 128; off > 0; off >>= 1) {
        if (threadIdx.x < off)
            red[threadIdx.x] = fmaxf(red[threadIdx.x], red[threadIdx.x + off]);
        __syncthreads();
    }
    m = red[0];
    __syncthreads();
    float s = 0.f;
#pragma unroll
    for (int i = 0; i < 8; i++) {
        v[i] = expf(v[i] - m);
        s += v[i];
    }
    red[threadIdx.x] = s;
    __syncthreads();
    for (int off = 128; off > 0; off >>= 1) {
        if (threadIdx.x < off)
            red[threadIdx.x] += red[threadIdx.x + off];
        __syncthreads();
    }
    float inv = 1.f / red[0];
#pragma unroll
    for (int i = 0; i < 8; i++) p[threadIdx.x + i * 256] = v[i] * inv;
}

// ---------------- AV: per (b,h): attn[S,S] @ V[S,64] -> vals[B,S,D] ---------
__global__ void av_kernel(const float* __restrict__ logits,
                          const float* __restrict__ qkv,
                          float* __restrict__ vals) {
    const int BM = 128, BN = 64, BK = 8;
    __shared__ float As[BK][BM];
    __shared__ float Bs[BK][BN];
    int tid = threadIdx.x;   // 256 threads
    int z = blockIdx.z;
    int b = z / Hh, h = z - b * Hh;
    const float* Ab = logits + (size_t)z * Ss * Ss;
    const float* Vb = qkv + (size_t)b * Ss * D3 + h * 192 + 128;
    int row0 = blockIdx.y * BM;
    int aRow = tid >> 1, aCol = (tid & 1) * 4;
    int bRow = tid >> 5, bCol = (tid & 31) * 2;
    int ty = tid >> 4, tx = tid & 15;   // TM=8 rows, TN=4 cols
    float acc[8][4] = {};
    for (int k0 = 0; k0 < Ss; k0 += BK) {
        float4 a4 = *(const float4*)(Ab + (size_t)(row0 + aRow) * Ss + k0 + aCol);
        As[aCol + 0][aRow] = a4.x;
        As[aCol + 1][aRow] = a4.y;
        As[aCol + 2][aRow] = a4.z;
        As[aCol + 3][aRow] = a4.w;
        float2 v2 = *(const float2*)(Vb + (size_t)(k0 + bRow) * D3 + bCol);
        Bs[bRow][bCol]     = v2.x;
        Bs[bRow][bCol + 1] = v2.y;
        __syncthreads();
#pragma unroll
        for (int kk = 0; kk < BK; kk++) {
            float ra[8], rb[4];
#pragma unroll
            for (int i = 0; i < 8; i++) ra[i] = As[kk][ty * 8 + i];
#pragma unroll
            for (int j = 0; j < 4; j++) rb[j] = Bs[kk][tx * 4 + j];
#pragma unroll
            for (int i = 0; i < 8; i++)
#pragma unroll
                for (int j = 0; j < 4; j++) acc[i][j] += ra[i] * rb[j];
        }
        __syncthreads();
    }
#pragma unroll
    for (int i = 0; i < 8; i++) {
        size_t r = (size_t)b * Ss + row0 + ty * 8 + i;
#pragma unroll
        for (int j = 0; j < 4; j++) {
            vals[r * Dd + h * 64 + tx * 4 + j] = acc[i][j];
        }
    }
}

// ---------------- host launch ----------------------------------------------
extern "C" void kernel_launch(void* const* d_in, const int* in_sizes, int n_in,
                              void* d_out, int out_size) {
    const float* x     = (const float*)d_in[0];
    const float* qkv_w = (const float*)d_in[1];
    const float* qkv_b = (const float*)d_in[2];
    const float* out_w = (const float*)d_in[3];
    const float* out_b = (const float*)d_in[4];
    const float* ln1_w = (const float*)d_in[5];
    const float* ln1_b = (const float*)d_in[6];
    const float* fc1_w = (const float*)d_in[7];
    const float* fc1_b = (const float*)d_in[8];
    const float* fc2_w = (const float*)d_in[9];
    const float* fc2_b = (const float*)d_in[10];
    const float* ln2_w = (const float*)d_in[11];
    const float* ln2_b = (const float*)d_in[12];

    float *xb, *hb, *qkvb, *lg, *vb, *fb;
    cudaGetSymbolAddress((void**)&xb,  g_x);
    cudaGetSymbolAddress((void**)&hb,  g_h);
    cudaGetSymbolAddress((void**)&qkvb,g_qkv);
    cudaGetSymbolAddress((void**)&lg,  g_logits);
    cudaGetSymbolAddress((void**)&vb,  g_vals);
    cudaGetSymbolAddress((void**)&fb,  g_ffn);

    const int nElem = MTOK * Dd;           // 3,145,728
    const int n4 = nElem / 4;

    // x -> g_x
    copy4_kernel<<<(n4 + 255) / 256, 256>>>((const float4*)x, (float4*)xb, n4);

    for (int l = 0; l < Ll; l++) {
        const float* qw  = qkv_w + (size_t)l * Dd * D3;
        const float* qbb = qkv_b + (size_t)l * D3;
        const float* ow  = out_w + (size_t)l * Dd * Dd;
        const float* ob  = out_b + (size_t)l * Dd;
        const float* l1w = ln1_w + (size_t)l * Dd;
        const float* l1b = ln1_b + (size_t)l * Dd;
        const float* f1w = fc1_w + (size_t)l * Dd * Ii;
        const float* f1b = fc1_b + (size_t)l * Ii;
        const float* f2w = fc2_w + (size_t)l * Ii * Dd;
        const float* f2b = fc2_b + (size_t)l * Dd;
        const float* l2w = ln2_w + (size_t)l * Dd;
        const float* l2b = ln2_b + (size_t)l * Dd;

        // 1. h = LN1(x)
        ln_kernel<<<MTOK, 256>>>(xb, l1w, l1b, hb);
        // 2. qkv = h @ qkv_w + qkv_b        (M=4096, N=2304, K=768)
        gemm128_kernel<false, false><<<dim3(D3 / 128, MTOK / 128), 256>>>(
            MTOK, D3, Dd, hb, qw, qbb, nullptr, qkvb);
        // 3. logits = Q @ K^T * scale
        logits_kernel<<<dim3(Ss / 128, Ss / 128, Bb * Hh), 256>>>(qkvb, lg);
        // 4. softmax rows
        softmax_kernel<<<Bb * Hh * Ss, 256>>>(lg);
        // 5. vals = attn @ V
        av_kernel<<<dim3(1, Ss / 128, Bb * Hh), 256>>>(lg, qkvb, vb);
        // 6. x = x + vals @ out_w + out_b   (M=4096, N=768, K=768)
        gemm128_kernel<false, true><<<dim3(Dd / 128, MTOK / 128), 256>>>(
            MTOK, Dd, Dd, vb, ow, ob, xb, xb);
        // 7. h = LN2(x)
        ln_kernel<<<MTOK, 256>>>(xb, l2w, l2b, hb);
        // 8. ffn = gelu(h @ fc1_w + fc1_b)  (M=4096, N=3072, K=768)
        gemm128_kernel<true, false><<<dim3(Ii / 128, MTOK / 128), 256>>>(
            MTOK, Ii, Dd, hb, f1w, f1b, nullptr, fb);
        // 9. x = x + ffn @ fc2_w + fc2_b    (M=4096, N=768, K=3072)
        gemm128_kernel<false, true><<<dim3(Dd / 128, MTOK / 128), 256>>>(
            MTOK, Dd, Ii, fb, f2w, f2b, xb, xb);
    }

    // g_x -> d_out
    copy4_kernel<<<(n4 + 255) / 256, 256>>>((const float4*)xb, (float4*)d_out, n4);
}

// round 2
// speedup vs baseline: 2.3001x; 2.3001x over previous
#include <cuda_runtime.h>
#include <math.h>
#include <stdint.h>

// Problem constants
#define Bb   2
#define Ss   2048
#define Dd   768
#define Hh   12
#define Ii   3072
#define Ll   4
#define HDm  64
#define MTOK (Bb*Ss)          // 4096 tokens
#define D3   (3*Dd)           // 2304

// ---------------- scratch buffers (device globals; no allocation) -----------
__device__ float g_x   [MTOK*Dd];
__device__ float g_h   [MTOK*Dd];
__device__ float g_qkv [MTOK*D3];
__device__ float g_logits[(size_t)Bb*Hh*Ss*Ss];  // 402 MB
__device__ float g_vals[MTOK*Dd];
__device__ float g_ffn [MTOK*Ii];

// ---------------- tf32 helpers ----------------------------------------------
__device__ __forceinline__ uint32_t f2tf(float x) {
    uint32_t r; asm("cvt.rna.tf32.f32 %0, %1;" : "=r"(r) : "f"(x)); return r;
}
__device__ __forceinline__ void mma_tf32(float& c0, float& c1, float& c2, float& c3,
                                         uint32_t a0, uint32_t a1, uint32_t a2, uint32_t a3,
                                         uint32_t b0, uint32_t b1) {
    asm volatile("mma.sync.aligned.m16n8k8.row.col.f32.tf32.tf32.f32 "
                 "{%0,%1,%2,%3}, {%4,%5,%6,%7}, {%8,%9}, {%0,%1,%2,%3};"
                 : "+f"(c0), "+f"(c1), "+f"(c2), "+f"(c3)
                 : "r"(a0), "r"(a1), "r"(a2), "r"(a3), "r"(b0), "r"(b1));
}

// ---------------- utility: vectorized copy ---------------------------------
__global__ void copy4_kernel(const float4* __restrict__ in, float4* __restrict__ out, int n4) {
    int i = blockIdx.x * blockDim.x + threadIdx.x;
    if (i < n4) out[i] = in[i];
}

// ---------------- LayerNorm -------------------------------------------------
__global__ void ln_kernel(const float* __restrict__ x,
                          const float* __restrict__ w,
                          const float* __restrict__ b,
                          float* __restrict__ out) {
    int row = blockIdx.x;
    const float* xr = x + (size_t)row * Dd;
    float v[3];
    float lsum = 0.f, lsq = 0.f;
#pragma unroll
    for (int i = 0; i < 3; i++) {
        v[i] = xr[threadIdx.x + i * 256];
        lsum += v[i];
        lsq  += v[i] * v[i];
    }
    __shared__ float s1[256], s2[256];
    s1[threadIdx.x] = lsum; s2[threadIdx.x] = lsq;
    __syncthreads();
    for (int off = 128; off > 0; off >>= 1) {
        if (threadIdx.x < off) {
            s1[threadIdx.x] += s1[threadIdx.x + off];
            s2[threadIdx.x] += s2[threadIdx.x + off];
        }
        __syncthreads();
    }
    float mean = s1[0] * (1.f / 768.f);
    float var  = s2[0] * (1.f / 768.f) - mean * mean;
    float inv  = rsqrtf(var + 1e-5f);
#pragma unroll
    for (int i = 0; i < 3; i++) {
        int c = threadIdx.x + i * 256;
        out[(size_t)row * Dd + c] = (v[i] - mean) * inv * w[c] + b[c];
    }
}

// ---------------- TF32 tensor-core GEMM: C = A[MxK]@B[KxN] + bias (+gelu/res)
// BM=128, BN=128, BK=16, 256 threads = 8 warps (2x4), warp tile 64x32.
template<bool GELU, bool RES>
__global__ __launch_bounds__(256) void gemm_tf32(int M, int N, int K,
                               const float* __restrict__ A,
                               const float* __restrict__ Bm,
                               const float* __restrict__ bias,
                               const float* __restrict__ res,
                               float* __restrict__ C) {
    __shared__ uint32_t As[16][136];
    __shared__ uint32_t Bs[16][136];
    int tid  = threadIdx.x;
    int lane = tid & 31, wid = tid >> 5;
    int wm = (wid >> 2) * 64;       // 0 / 64
    int wn = (wid & 3) * 32;        // 0..96
    int qr = lane >> 2, qc = lane & 3;
    int row0 = blockIdx.y * 128, col0 = blockIdx.x * 128;

    float acc[4][4][4] = {};

    for (int k0 = 0; k0 < K; k0 += 16) {
        // A tile: 128x16 -> As[k][m] (transposed scatter)
#pragma unroll
        for (int i = 0; i < 2; i++) {
            int idx = tid * 2 + i;
            int m = idx >> 2, kc = (idx & 3) * 4;
            float4 a4 = *(const float4*)(A + (size_t)(row0 + m) * K + k0 + kc);
            As[kc + 0][m] = f2tf(a4.x);
            As[kc + 1][m] = f2tf(a4.y);
            As[kc + 2][m] = f2tf(a4.z);
            As[kc + 3][m] = f2tf(a4.w);
        }
        // B tile: 16x128 -> Bs[k][n]
#pragma unroll
        for (int i = 0; i < 2; i++) {
            int idx = tid * 2 + i;
            int k = idx >> 5, nc = (idx & 31) * 4;
            float4 b4 = *(const float4*)(Bm + (size_t)(k0 + k) * N + col0 + nc);
            uint4 t;
            t.x = f2tf(b4.x); t.y = f2tf(b4.y); t.z = f2tf(b4.z); t.w = f2tf(b4.w);
            *(uint4*)&Bs[k][nc] = t;
        }
        __syncthreads();
#pragma unroll
        for (int ks = 0; ks < 16; ks += 8) {
            uint32_t af[4][4], bf[4][2];
#pragma unroll
            for (int i = 0; i < 4; i++) {
                int m = wm + i * 16 + qr;
                af[i][0] = As[ks + qc][m];
                af[i][1] = As[ks + qc][m + 8];
                af[i][2] = As[ks + qc + 4][m];
                af[i][3] = As[ks + qc + 4][m + 8];
            }
#pragma unroll
            for (int j = 0; j < 4; j++) {
                int n = wn + j * 8 + qr;
                bf[j][0] = Bs[ks + qc][n];
                bf[j][1] = Bs[ks + qc + 4][n];
            }
#pragma unroll
            for (int i = 0; i < 4; i++)
#pragma unroll
                for (int j = 0; j < 4; j++)
                    mma_tf32(acc[i][j][0], acc[i][j][1], acc[i][j][2], acc[i][j][3],
                             af[i][0], af[i][1], af[i][2], af[i][3],
                             bf[j][0], bf[j][1]);
        }
        __syncthreads();
    }
    // epilogue
#pragma unroll
    for (int i = 0; i < 4; i++) {
        int r0 = row0 + wm + i * 16 + qr;
        int r1 = r0 + 8;
#pragma unroll
        for (int j = 0; j < 4; j++) {
            int c0 = col0 + wn + j * 8 + qc * 2;
            float v0 = acc[i][j][0] + bias[c0];
            float v1 = acc[i][j][1] + bias[c0 + 1];
            float v2 = acc[i][j][2] + bias[c0];
            float v3 = acc[i][j][3] + bias[c0 + 1];
            if (GELU) {
                v0 = 0.5f * v0 * (1.0f + erff(v0 * 0.70710678f));
                v1 = 0.5f * v1 * (1.0f + erff(v1 * 0.70710678f));
                v2 = 0.5f * v2 * (1.0f + erff(v2 * 0.70710678f));
                v3 = 0.5f * v3 * (1.0f + erff(v3 * 0.70710678f));
            }
            if (RES) {
                float2 r0v = *(const float2*)(res + (size_t)r0 * N + c0);
                float2 r1v = *(const float2*)(res + (size_t)r1 * N + c0);
                v0 += r0v.x; v1 += r0v.y; v2 += r1v.x; v3 += r1v.y;
            }
            *(float2*)(C + (size_t)r0 * N + c0) = make_float2(v0, v1);
            *(float2*)(C + (size_t)r1 * N + c0) = make_float2(v2, v3);
        }
    }
}

// ---------------- logits: per (b,h) Q[S,64] @ K[S,64]^T * scale (TF32 mma) --
__global__ __launch_bounds__(256) void logits_tf32(const float* __restrict__ qkv,
                                                   float* __restrict__ logits) {
    __shared__ uint32_t As[16][136];
    __shared__ uint32_t Bs[16][136];
    int tid  = threadIdx.x;
    int lane = tid & 31, wid = tid >> 5;
    int wm = (wid >> 2) * 64;
    int wn = (wid & 3) * 32;
    int qr = lane >> 2, qc = lane & 3;
    int z = blockIdx.z;
    int b = z / Hh, h = z - b * Hh;
    const float* Qb = qkv + (size_t)b * Ss * D3 + h * 192;
    const float* Kb = Qb + 64;
    int row0 = blockIdx.y * 128, col0 = blockIdx.x * 128;

    float acc[4][4][4] = {};

    for (int k0 = 0; k0 < HDm; k0 += 16) {
#pragma unroll
        for (int i = 0; i < 2; i++) {
            int idx = tid * 2 + i;
            int m = idx >> 2, kc = (idx & 3) * 4;
            float4 a4 = *(const float4*)(Qb + (size_t)(row0 + m) * D3 + k0 + kc);
            As[kc + 0][m] = f2tf(a4.x);
            As[kc + 1][m] = f2tf(a4.y);
            As[kc + 2][m] = f2tf(a4.z);
            As[kc + 3][m] = f2tf(a4.w);
            float4 k4 = *(const float4*)(Kb + (size_t)(col0 + m) * D3 + k0 + kc);
            Bs[kc + 0][m] = f2tf(k4.x);
            Bs[kc + 1][m] = f2tf(k4.y);
            Bs[kc + 2][m] = f2tf(k4.z);
            Bs[kc + 3][m] = f2tf(k4.w);
        }
        __syncthreads();
#pragma unroll
        for (int ks = 0; ks < 16; ks += 8) {
            uint32_t af[4][4], bf[4][2];
#pragma unroll
            for (int i = 0; i < 4; i++) {
                int m = wm + i * 16 + qr;
                af[i][0] = As[ks + qc][m];
                af[i][1] = As[ks + qc][m + 8];
                af[i][2] = As[ks + qc + 4][m];
                af[i][3] = As[ks + qc + 4][m + 8];
            }
#pragma unroll
            for (int j = 0; j < 4; j++) {
                int n = wn + j * 8 + qr;
                bf[j][0] = Bs[ks + qc][n];
                bf[j][1] = Bs[ks + qc + 4][n];
            }
#pragma unroll
            for (int i = 0; i < 4; i++)
#pragma unroll
                for (int j = 0; j < 4; j++)
                    mma_tf32(acc[i][j][0], acc[i][j][1], acc[i][j][2], acc[i][j][3],
                             af[i][0], af[i][1], af[i][2], af[i][3],
                             bf[j][0], bf[j][1]);
        }
        __syncthreads();
    }
    float* Cb = logits + (size_t)z * Ss * Ss;
#pragma unroll
    for (int i = 0; i < 4; i++) {
        size_t r0 = row0 + wm + i * 16 + qr;
        size_t r1 = r0 + 8;
#pragma unroll
        for (int j = 0; j < 4; j++) {
            int c0 = col0 + wn + j * 8 + qc * 2;
            *(float2*)(Cb + r0 * Ss + c0) = make_float2(acc[i][j][0] * 0.125f, acc[i][j][1] * 0.125f);
            *(float2*)(Cb + r1 * Ss + c0) = make_float2(acc[i][j][2] * 0.125f, acc[i][j][3] * 0.125f);
        }
    }
}

// ---------------- row softmax over 2048 elements ----------------------------
__global__ void softmax_kernel(float* __restrict__ logits) {
    size_t row = blockIdx.x;
    float* p = logits + row * (size_t)Ss;
    float v[8];
    float m = -1e30f;
#pragma unroll
    for (int i = 0; i < 8; i++) {
        v[i] = p[threadIdx.x + i * 256];
        m = fmaxf(m, v[i]);
    }
    __shared__ float red[256];
    red[threadIdx.x] = m;
    __syncthreads();
    for (int off = 128; off > 0; off >>= 1) {
        if (threadIdx.x < off)
            red[threadIdx.x] = fmaxf(red[threadIdx.x], red[threadIdx.x + off]);
        __syncthreads();
    }
    m = red[0];
    __syncthreads();
    float s = 0.f;
#pragma unroll
    for (int i = 0; i < 8; i++) {
        v[i] = expf(v[i] - m);
        s += v[i];
    }
    red[threadIdx.x] = s;
    __syncthreads();
    for (int off = 128; off > 0; off >>= 1) {
        if (threadIdx.x < off)
            red[threadIdx.x] += red[threadIdx.x + off];
        __syncthreads();
    }
    float inv = 1.f / red[0];
#pragma unroll
    for (int i = 0; i < 8; i++) p[threadIdx.x + i * 256] = v[i] * inv;
}

// ---------------- AV: per (b,h) attn[S,S] @ V[S,64] (TF32 mma) --------------
// BM=128, BN=64, BK=16, 8 warps (4x2), warp tile 32x32.
__global__ __launch_bounds__(256) void av_tf32(const float* __restrict__ logits,
                                               const float* __restrict__ qkv,
                                               float* __restrict__ vals) {
    __shared__ uint32_t As[16][136];
    __shared__ uint32_t Bs[16][72];
    int tid  = threadIdx.x;
    int lane = tid & 31, wid = tid >> 5;
    int wm = (wid >> 1) * 32;      // 0..96
    int wn = (wid & 1) * 32;       // 0 / 32
    int qr = lane >> 2, qc = lane & 3;
    int z = blockIdx.z;
    int b = z / Hh, h = z - b * Hh;
    const float* Ab = logits + (size_t)z * Ss * Ss;
    const float* Vb = qkv + (size_t)b * Ss * D3 + h * 192 + 128;
    int row0 = blockIdx.y * 128;

    float acc[2][4][4] = {};

    for (int k0 = 0; k0 < Ss; k0 += 16) {
#pragma unroll
        for (int i = 0; i < 2; i++) {
            int idx = tid * 2 + i;
            int m = idx >> 2, kc = (idx & 3) * 4;
            float4 a4 = *(const float4*)(Ab + (size_t)(row0 + m) * Ss + k0 + kc);
            As[kc + 0][m] = f2tf(a4.x);
            As[kc + 1][m] = f2tf(a4.y);
            As[kc + 2][m] = f2tf(a4.z);
            As[kc + 3][m] = f2tf(a4.w);
        }
        {
            int k = tid >> 4, nc = (tid & 15) * 4;
            float4 v4 = *(const float4*)(Vb + (size_t)(k0 + k) * D3 + nc);
            uint4 t;
            t.x = f2tf(v4.x); t.y = f2tf(v4.y); t.z = f2tf(v4.z); t.w = f2tf(v4.w);
            *(uint4*)&Bs[k][nc] = t;
        }
        __syncthreads();
#pragma unroll
        for (int ks = 0; ks < 16; ks += 8) {
            uint32_t af[2][4], bf[4][2];
#pragma unroll
            for (int i = 0; i < 2; i++) {
                int m = wm + i * 16 + qr;
                af[i][0] = As[ks + qc][m];
                af[i][1] = As[ks + qc][m + 8];
                af[i][2] = As[ks + qc + 4][m];
                af[i][3] = As[ks + qc + 4][m + 8];
            }
#pragma unroll
            for (int j = 0; j < 4; j++) {
                int n = wn + j * 8 + qr;
                bf[j][0] = Bs[ks + qc][n];
                bf[j][1] = Bs[ks + qc + 4][n];
            }
#pragma unroll
            for (int i = 0; i < 2; i++)
#pragma unroll
                for (int j = 0; j < 4; j++)
                    mma_tf32(acc[i][j][0], acc[i][j][1], acc[i][j][2], acc[i][j][3],
                             af[i][0], af[i][1], af[i][2], af[i][3],
                             bf[j][0], bf[j][1]);
        }
        __syncthreads();
    }
#pragma unroll
    for (int i = 0; i < 2; i++) {
        size_t r0 = (size_t)b * Ss + row0 + wm + i * 16 + qr;
        size_t r1 = r0 + 8;
#pragma unroll
        for (int j = 0; j < 4; j++) {
            int c0 = h * 64 + wn + j * 8 + qc * 2;
            *(float2*)(vals + r0 * Dd + c0) = make_float2(acc[i][j][0], acc[i][j][1]);
            *(float2*)(vals + r1 * Dd + c0) = make_float2(acc[i][j][2], acc[i][j][3]);
        }
    }
}

// ---------------- host launch ----------------------------------------------
extern "C" void kernel_launch(void* const* d_in, const int* in_sizes, int n_in,
                              void* d_out, int out_size) {
    const float* x     = (const float*)d_in[0];
    const float* qkv_w = (const float*)d_in[1];
    const float* qkv_b = (const float*)d_in[2];
    const float* out_w = (const float*)d_in[3];
    const float* out_b = (const float*)d_in[4];
    const float* ln1_w = (const float*)d_in[5];
    const float* ln1_b = (const float*)d_in[6];
    const float* fc1_w = (const float*)d_in[7];
    const float* fc1_b = (const float*)d_in[8];
    const float* fc2_w = (const float*)d_in[9];
    const float* fc2_b = (const float*)d_in[10];
    const float* ln2_w = (const float*)d_in[11];
    const float* ln2_b = (const float*)d_in[12];

    float *xb, *hb, *qkvb, *lg, *vb, *fb;
    cudaGetSymbolAddress((void**)&xb,  g_x);
    cudaGetSymbolAddress((void**)&hb,  g_h);
    cudaGetSymbolAddress((void**)&qkvb,g_qkv);
    cudaGetSymbolAddress((void**)&lg,  g_logits);
    cudaGetSymbolAddress((void**)&vb,  g_vals);
    cudaGetSymbolAddress((void**)&fb,  g_ffn);

    const int nElem = MTOK * Dd;
    const int n4 = nElem / 4;

    copy4_kernel<<<(n4 + 255) / 256, 256>>>((const float4*)x, (float4*)xb, n4);

    for (int l = 0; l < Ll; l++) {
        const float* qw  = qkv_w + (size_t)l * Dd * D3;
        const float* qbb = qkv_b + (size_t)l * D3;
        const float* ow  = out_w + (size_t)l * Dd * Dd;
        const float* ob  = out_b + (size_t)l * Dd;
        const float* l1w = ln1_w + (size_t)l * Dd;
        const float* l1b = ln1_b + (size_t)l * Dd;
        const float* f1w = fc1_w + (size_t)l * Dd * Ii;
        const float* f1b = fc1_b + (size_t)l * Ii;
        const float* f2w = fc2_w + (size_t)l * Ii * Dd;
        const float* f2b = fc2_b + (size_t)l * Dd;
        const float* l2w = ln2_w + (size_t)l * Dd;
        const float* l2b = ln2_b + (size_t)l * Dd;

        ln_kernel<<<MTOK, 256>>>(xb, l1w, l1b, hb);
        gemm_tf32<false, false><<<dim3(D3 / 128, MTOK / 128), 256>>>(
            MTOK, D3, Dd, hb, qw, qbb, nullptr, qkvb);
        logits_tf32<<<dim3(Ss / 128, Ss / 128, Bb * Hh), 256>>>(qkvb, lg);
        softmax_kernel<<<Bb * Hh * Ss, 256>>>(lg);
        av_tf32<<<dim3(1, Ss / 128, Bb * Hh), 256>>>(lg, qkvb, vb);
        gemm_tf32<false, true><<<dim3(Dd / 128, MTOK / 128), 256>>>(
            MTOK, Dd, Dd, vb, ow, ob, xb, xb);
        ln_kernel<<<MTOK, 256>>>(xb, l2w, l2b, hb);
        gemm_tf32<true, false><<<dim3(Ii / 128, MTOK / 128), 256>>>(
            MTOK, Ii, Dd, hb, f1w, f1b, nullptr, fb);
        gemm_tf32<false, true><<<dim3(Dd / 128, MTOK / 128), 256>>>(
            MTOK, Dd, Ii, fb, f2w, f2b, xb, xb);
    }

    copy4_kernel<<<(n4 + 255) / 256, 256>>>((const float4*)xb, (float4*)d_out, n4);
}

// round 3
// speedup vs baseline: 2.8348x; 1.2325x over previous
#include <cuda_runtime.h>
#include <math.h>
#include <stdint.h>

// Problem constants
#define Bb   2
#define Ss   2048
#define Dd   768
#define Hh   12
#define Ii   3072
#define Ll   4
#define HDm  64
#define MTOK (Bb*Ss)          // 4096 tokens
#define D3   (3*Dd)           // 2304

// ---------------- scratch buffers (device globals; no allocation) -----------
__device__ float g_x   [MTOK*Dd];
__device__ float g_h   [MTOK*Dd];
__device__ float g_qkv [MTOK*D3];
__device__ float g_vals[MTOK*Dd];
__device__ float g_ffn [MTOK*Ii];

// ---------------- tf32 helpers ----------------------------------------------
__device__ __forceinline__ uint32_t f2tf(float x) {
    uint32_t r; asm("cvt.rna.tf32.f32 %0, %1;" : "=r"(r) : "f"(x)); return r;
}
__device__ __forceinline__ void mma_tf32(float& c0, float& c1, float& c2, float& c3,
                                         uint32_t a0, uint32_t a1, uint32_t a2, uint32_t a3,
                                         uint32_t b0, uint32_t b1) {
    asm volatile("mma.sync.aligned.m16n8k8.row.col.f32.tf32.tf32.f32 "
                 "{%0,%1,%2,%3}, {%4,%5,%6,%7}, {%8,%9}, {%0,%1,%2,%3};"
                 : "+f"(c0), "+f"(c1), "+f"(c2), "+f"(c3)
                 : "r"(a0), "r"(a1), "r"(a2), "r"(a3), "r"(b0), "r"(b1));
}

// ---------------- utility: vectorized copy ---------------------------------
__global__ void copy4_kernel(const float4* __restrict__ in, float4* __restrict__ out, int n4) {
    int i = blockIdx.x * blockDim.x + threadIdx.x;
    if (i < n4) out[i] = in[i];
}

// ---------------- LayerNorm -------------------------------------------------
__global__ void ln_kernel(const float* __restrict__ x,
                          const float* __restrict__ w,
                          const float* __restrict__ b,
                          float* __restrict__ out) {
    int row = blockIdx.x;
    const float* xr = x + (size_t)row * Dd;
    float v[3];
    float lsum = 0.f, lsq = 0.f;
#pragma unroll
    for (int i = 0; i < 3; i++) {
        v[i] = xr[threadIdx.x + i * 256];
        lsum += v[i];
        lsq  += v[i] * v[i];
    }
    __shared__ float s1[256], s2[256];
    s1[threadIdx.x] = lsum; s2[threadIdx.x] = lsq;
    __syncthreads();
    for (int off = 128; off > 0; off >>= 1) {
        if (threadIdx.x < off) {
            s1[threadIdx.x] += s1[threadIdx.x + off];
            s2[threadIdx.x] += s2[threadIdx.x + off];
        }
        __syncthreads();
    }
    float mean = s1[0] * (1.f / 768.f);
    float var  = s2[0] * (1.f / 768.f) - mean * mean;
    float inv  = rsqrtf(var + 1e-5f);
#pragma unroll
    for (int i = 0; i < 3; i++) {
        int c = threadIdx.x + i * 256;
        out[(size_t)row * Dd + c] = (v[i] - mean) * inv * w[c] + b[c];
    }
}

// ---------------- TF32 tensor-core GEMM (unchanged from R2) ------------------
template<bool GELU, bool RES>
__global__ __launch_bounds__(256) void gemm_tf32(int M, int N, int K,
                               const float* __restrict__ A,
                               const float* __restrict__ Bm,
                               const float* __restrict__ bias,
                               const float* __restrict__ res,
                               float* __restrict__ C) {
    __shared__ uint32_t As[16][136];
    __shared__ uint32_t Bs[16][136];
    int tid  = threadIdx.x;
    int lane = tid & 31, wid = tid >> 5;
    int wm = (wid >> 2) * 64;
    int wn = (wid & 3) * 32;
    int qr = lane >> 2, qc = lane & 3;
    int row0 = blockIdx.y * 128, col0 = blockIdx.x * 128;

    float acc[4][4][4] = {};

    for (int k0 = 0; k0 < K; k0 += 16) {
#pragma unroll
        for (int i = 0; i < 2; i++) {
            int idx = tid * 2 + i;
            int m = idx >> 2, kc = (idx & 3) * 4;
            float4 a4 = *(const float4*)(A + (size_t)(row0 + m) * K + k0 + kc);
            As[kc + 0][m] = f2tf(a4.x);
            As[kc + 1][m] = f2tf(a4.y);
            As[kc + 2][m] = f2tf(a4.z);
            As[kc + 3][m] = f2tf(a4.w);
        }
#pragma unroll
        for (int i = 0; i < 2; i++) {
            int idx = tid * 2 + i;
            int k = idx >> 5, nc = (idx & 31) * 4;
            float4 b4 = *(const float4*)(Bm + (size_t)(k0 + k) * N + col0 + nc);
            uint4 t;
            t.x = f2tf(b4.x); t.y = f2tf(b4.y); t.z = f2tf(b4.z); t.w = f2tf(b4.w);
            *(uint4*)&Bs[k][nc] = t;
        }
        __syncthreads();
#pragma unroll
        for (int ks = 0; ks < 16; ks += 8) {
            uint32_t af[4][4], bf[4][2];
#pragma unroll
            for (int i = 0; i < 4; i++) {
                int m = wm + i * 16 + qr;
                af[i][0] = As[ks + qc][m];
                af[i][1] = As[ks + qc][m + 8];
                af[i][2] = As[ks + qc + 4][m];
                af[i][3] = As[ks + qc + 4][m + 8];
            }
#pragma unroll
            for (int j = 0; j < 4; j++) {
                int n = wn + j * 8 + qr;
                bf[j][0] = Bs[ks + qc][n];
                bf[j][1] = Bs[ks + qc + 4][n];
            }
#pragma unroll
            for (int i = 0; i < 4; i++)
#pragma unroll
                for (int j = 0; j < 4; j++)
                    mma_tf32(acc[i][j][0], acc[i][j][1], acc[i][j][2], acc[i][j][3],
                             af[i][0], af[i][1], af[i][2], af[i][3],
                             bf[j][0], bf[j][1]);
        }
        __syncthreads();
    }
#pragma unroll
    for (int i = 0; i < 4; i++) {
        int r0 = row0 + wm + i * 16 + qr;
        int r1 = r0 + 8;
#pragma unroll
        for (int j = 0; j < 4; j++) {
            int c0 = col0 + wn + j * 8 + qc * 2;
            float v0 = acc[i][j][0] + bias[c0];
            float v1 = acc[i][j][1] + bias[c0 + 1];
            float v2 = acc[i][j][2] + bias[c0];
            float v3 = acc[i][j][3] + bias[c0 + 1];
            if (GELU) {
                v0 = 0.5f * v0 * (1.0f + erff(v0 * 0.70710678f));
                v1 = 0.5f * v1 * (1.0f + erff(v1 * 0.70710678f));
                v2 = 0.5f * v2 * (1.0f + erff(v2 * 0.70710678f));
                v3 = 0.5f * v3 * (1.0f + erff(v3 * 0.70710678f));
            }
            if (RES) {
                float2 r0v = *(const float2*)(res + (size_t)r0 * N + c0);
                float2 r1v = *(const float2*)(res + (size_t)r1 * N + c0);
                v0 += r0v.x; v1 += r0v.y; v2 += r1v.x; v3 += r1v.y;
            }
            *(float2*)(C + (size_t)r0 * N + c0) = make_float2(v0, v1);
            *(float2*)(C + (size_t)r1 * N + c0) = make_float2(v2, v3);
        }
    }
}

// ---------------- fused flash attention (tf32 mma, online softmax) -----------
// grid (16 q-tiles, 24 bh), 256 threads = 8 warps; each warp owns 16 q-rows.
// smem: Ks[128][72] (tf32) + Vs[128][72] (tf32) + P panes 8x[16][132] (tf32)
#define KSTR 72
#define PSTR 132
#define FLASH_SMEM ((2*128*KSTR + 8*16*PSTR) * 4)

__global__ __launch_bounds__(256, 1) void flash_tf32(const float* __restrict__ qkv,
                                                     float* __restrict__ vals) {
    extern __shared__ uint32_t sm[];
    uint32_t* Ks   = sm;
    uint32_t* Vs   = sm + 128 * KSTR;
    uint32_t* Pall = sm + 2 * 128 * KSTR;

    int tid = threadIdx.x, lane = tid & 31, wid = tid >> 5;
    int qr = lane >> 2, qc = lane & 3;
    int z = blockIdx.y, b = z / Hh, h = z - b * Hh;
    const float* Qb = qkv + (size_t)b * Ss * D3 + h * 192;
    const float* Kb = Qb + 64;
    const float* Vb = Qb + 128;
    int row0 = blockIdx.x * 128;
    uint32_t* Pw = Pall + wid * 16 * PSTR;
    int wrow = wid * 16;

    // ---- stage Q (pre-scaled, tf32) via Pall scratch, then lift to fragments
    for (int i = tid; i < 2048; i += 256) {
        int t = i >> 4, d = (i & 15) << 2;
        float4 q4 = *(const float4*)(Qb + (size_t)(row0 + t) * D3 + d);
        uint32_t* dst = Pall + t * KSTR + d;
        dst[0] = f2tf(q4.x * 0.125f);
        dst[1] = f2tf(q4.y * 0.125f);
        dst[2] = f2tf(q4.z * 0.125f);
        dst[3] = f2tf(q4.w * 0.125f);
    }
    __syncthreads();
    uint32_t qa[8][4];
#pragma unroll
    for (int kc = 0; kc < 8; kc++) {
        qa[kc][0] = Pall[(wrow + qr)     * KSTR + kc * 8 + qc];
        qa[kc][1] = Pall[(wrow + qr + 8) * KSTR + kc * 8 + qc];
        qa[kc][2] = Pall[(wrow + qr)     * KSTR + kc * 8 + qc + 4];
        qa[kc][3] = Pall[(wrow + qr + 8) * KSTR + kc * 8 + qc + 4];
    }
    __syncthreads();

    float m0 = -1e30f, m1 = -1e30f, l0 = 0.f, l1 = 0.f;
    float o[8][4] = {};

    for (int kv = 0; kv < Ss; kv += 128) {
        // load K/V tiles (tf32-converted once here)
        for (int i = tid; i < 2048; i += 256) {
            int t = i >> 4, d = (i & 15) << 2;
            float4 k4 = *(const float4*)(Kb + (size_t)(kv + t) * D3 + d);
            float4 v4 = *(const float4*)(Vb + (size_t)(kv + t) * D3 + d);
            uint4 ku, vu;
            ku.x = f2tf(k4.x); ku.y = f2tf(k4.y); ku.z = f2tf(k4.z); ku.w = f2tf(k4.w);
            vu.x = f2tf(v4.x); vu.y = f2tf(v4.y); vu.z = f2tf(v4.z); vu.w = f2tf(v4.w);
            *(uint4*)(Ks + t * KSTR + d) = ku;
            *(uint4*)(Vs + t * KSTR + d) = vu;
        }
        __syncthreads();

        // ---- S = Qs @ K^T : 16 n-tiles of 8 cols, rows (wrow+qr, wrow+qr+8)
        float s[16][4];
#pragma unroll
        for (int j = 0; j < 16; j++) {
            s[j][0] = s[j][1] = s[j][2] = s[j][3] = 0.f;
#pragma unroll
            for (int kc = 0; kc < 8; kc++) {
                uint32_t b0 = Ks[(j * 8 + qr) * KSTR + kc * 8 + qc];
                uint32_t b1 = Ks[(j * 8 + qr) * KSTR + kc * 8 + qc + 4];
                mma_tf32(s[j][0], s[j][1], s[j][2], s[j][3],
                         qa[kc][0], qa[kc][1], qa[kc][2], qa[kc][3], b0, b1);
            }
        }

        // ---- online softmax (rows qr / qr+8 within this warp's 16 rows)
        float tm0 = -1e30f, tm1 = -1e30f;
#pragma unroll
        for (int j = 0; j < 16; j++) {
            tm0 = fmaxf(tm0, fmaxf(s[j][0], s[j][1]));
            tm1 = fmaxf(tm1, fmaxf(s[j][2], s[j][3]));
        }
        tm0 = fmaxf(tm0, __shfl_xor_sync(0xffffffffu, tm0, 1));
        tm0 = fmaxf(tm0, __shfl_xor_sync(0xffffffffu, tm0, 2));
        tm1 = fmaxf(tm1, __shfl_xor_sync(0xffffffffu, tm1, 1));
        tm1 = fmaxf(tm1, __shfl_xor_sync(0xffffffffu, tm1, 2));
        float mn0 = fmaxf(m0, tm0), mn1 = fmaxf(m1, tm1);
        float sc0 = __expf(m0 - mn0), sc1 = __expf(m1 - mn1);
        m0 = mn0; m1 = mn1;

        float ls0 = 0.f, ls1 = 0.f;
#pragma unroll
        for (int j = 0; j < 16; j++) {
            float p0 = __expf(s[j][0] - m0);
            float p1 = __expf(s[j][1] - m0);
            float p2 = __expf(s[j][2] - m1);
            float p3 = __expf(s[j][3] - m1);
            ls0 += p0 + p1; ls1 += p2 + p3;
            uint2 u0; u0.x = f2tf(p0); u0.y = f2tf(p1);
            uint2 u1; u1.x = f2tf(p2); u1.y = f2tf(p3);
            *(uint2*)(Pw + qr * PSTR + j * 8 + qc * 2)       = u0;
            *(uint2*)(Pw + (qr + 8) * PSTR + j * 8 + qc * 2) = u1;
        }
        ls0 += __shfl_xor_sync(0xffffffffu, ls0, 1);
        ls0 += __shfl_xor_sync(0xffffffffu, ls0, 2);
        ls1 += __shfl_xor_sync(0xffffffffu, ls1, 1);
        ls1 += __shfl_xor_sync(0xffffffffu, ls1, 2);
        l0 = l0 * sc0 + ls0;
        l1 = l1 * sc1 + ls1;
#pragma unroll
        for (int j = 0; j < 8; j++) {
            o[j][0] *= sc0; o[j][1] *= sc0; o[j][2] *= sc1; o[j][3] *= sc1;
        }
        __syncwarp();

        // ---- O += P @ V
#pragma unroll
        for (int kc = 0; kc < 16; kc++) {
            uint32_t a0 = Pw[qr * PSTR + kc * 8 + qc];
            uint32_t a1 = Pw[(qr + 8) * PSTR + kc * 8 + qc];
            uint32_t a2 = Pw[qr * PSTR + kc * 8 + qc + 4];
            uint32_t a3 = Pw[(qr + 8) * PSTR + kc * 8 + qc + 4];
#pragma unroll
            for (int j = 0; j < 8; j++) {
                uint32_t b0 = Vs[(kc * 8 + qc) * KSTR + j * 8 + qr];
                uint32_t b1 = Vs[(kc * 8 + qc + 4) * KSTR + j * 8 + qr];
                mma_tf32(o[j][0], o[j][1], o[j][2], o[j][3], a0, a1, a2, a3, b0, b1);
            }
        }
        __syncthreads();
    }

    // ---- epilogue: normalize by l and write out
    float inv0 = 1.f / l0, inv1 = 1.f / l1;
    size_t r0 = (size_t)b * Ss + row0 + wrow + qr;
    size_t r1 = r0 + 8;
#pragma unroll
    for (int j = 0; j < 8; j++) {
        int c0 = h * 64 + j * 8 + qc * 2;
        *(float2*)(vals + r0 * Dd + c0) = make_float2(o[j][0] * inv0, o[j][1] * inv0);
        *(float2*)(vals + r1 * Dd + c0) = make_float2(o[j][2] * inv1, o[j][3] * inv1);
    }
}

// ---------------- host launch ----------------------------------------------
extern "C" void kernel_launch(void* const* d_in, const int* in_sizes, int n_in,
                              void* d_out, int out_size) {
    const float* x     = (const float*)d_in[0];
    const float* qkv_w = (const float*)d_in[1];
    const float* qkv_b = (const float*)d_in[2];
    const float* out_w = (const float*)d_in[3];
    const float* out_b = (const float*)d_in[4];
    const float* ln1_w = (const float*)d_in[5];
    const float* ln1_b = (const float*)d_in[6];
    const float* fc1_w = (const float*)d_in[7];
    const float* fc1_b = (const float*)d_in[8];
    const float* fc2_w = (const float*)d_in[9];
    const float* fc2_b = (const float*)d_in[10];
    const float* ln2_w = (const float*)d_in[11];
    const float* ln2_b = (const float*)d_in[12];

    float *xb, *hb, *qkvb, *vb, *fb;
    cudaGetSymbolAddress((void**)&xb,  g_x);
    cudaGetSymbolAddress((void**)&hb,  g_h);
    cudaGetSymbolAddress((void**)&qkvb,g_qkv);
    cudaGetSymbolAddress((void**)&vb,  g_vals);
    cudaGetSymbolAddress((void**)&fb,  g_ffn);

    cudaFuncSetAttribute(flash_tf32, cudaFuncAttributeMaxDynamicSharedMemorySize, FLASH_SMEM);

    const int nElem = MTOK * Dd;
    const int n4 = nElem / 4;

    copy4_kernel<<<(n4 + 255) / 256, 256>>>((const float4*)x, (float4*)xb, n4);

    for (int l = 0; l < Ll; l++) {
        const float* qw  = qkv_w + (size_t)l * Dd * D3;
        const float* qbb = qkv_b + (size_t)l * D3;
        const float* ow  = out_w + (size_t)l * Dd * Dd;
        const float* ob  = out_b + (size_t)l * Dd;
        const float* l1w = ln1_w + (size_t)l * Dd;
        const float* l1b = ln1_b + (size_t)l * Dd;
        const float* f1w = fc1_w + (size_t)l * Dd * Ii;
        const float* f1b = fc1_b + (size_t)l * Ii;
        const float* f2w = fc2_w + (size_t)l * Ii * Dd;
        const float* f2b = fc2_b + (size_t)l * Dd;
        const float* l2w = ln2_w + (size_t)l * Dd;
        const float* l2b = ln2_b + (size_t)l * Dd;

        ln_kernel<<<MTOK, 256>>>(xb, l1w, l1b, hb);
        gemm_tf32<false, false><<<dim3(D3 / 128, MTOK / 128), 256>>>(
            MTOK, D3, Dd, hb, qw, qbb, nullptr, qkvb);
        flash_tf32<<<dim3(Ss / 128, Bb * Hh), 256, FLASH_SMEM>>>(qkvb, vb);
        gemm_tf32<false, true><<<dim3(Dd / 128, MTOK / 128), 256>>>(
            MTOK, Dd, Dd, vb, ow, ob, xb, xb);
        ln_kernel<<<MTOK, 256>>>(xb, l2w, l2b, hb);
        gemm_tf32<true, false><<<dim3(Ii / 128, MTOK / 128), 256>>>(
            MTOK, Ii, Dd, hb, f1w, f1b, nullptr, fb);
        gemm_tf32<false, true><<<dim3(Dd / 128, MTOK / 128), 256>>>(
            MTOK, Dd, Ii, fb, f2w, f2b, xb, xb);
    }

    copy4_kernel<<<(n4 + 255) / 256, 256>>>((const float4*)xb, (float4*)d_out, n4);
}

// round 4
// speedup vs baseline: 2.9480x; 1.0399x over previous
#include <cuda_runtime.h>
#include <math.h>
#include <stdint.h>

// Problem constants
#define Bb   2
#define Ss   2048
#define Dd   768
#define Hh   12
#define Ii   3072
#define Ll   4
#define HDm  64
#define MTOK (Bb*Ss)          // 4096 tokens
#define D3   (3*Dd)           // 2304

// ---------------- scratch buffers (device globals; no allocation) -----------
__device__ float g_x   [MTOK*Dd];
__device__ float g_h   [MTOK*Dd];
__device__ float g_qkv [MTOK*D3];
__device__ float g_vals[MTOK*Dd];
__device__ float g_ffn [MTOK*Ii];

// ---------------- tf32 helpers ----------------------------------------------
__device__ __forceinline__ uint32_t f2tf(float x) {
    uint32_t r; asm("cvt.rna.tf32.f32 %0, %1;" : "=r"(r) : "f"(x)); return r;
}
__device__ __forceinline__ void mma_tf32(float& c0, float& c1, float& c2, float& c3,
                                         uint32_t a0, uint32_t a1, uint32_t a2, uint32_t a3,
                                         uint32_t b0, uint32_t b1) {
    asm volatile("mma.sync.aligned.m16n8k8.row.col.f32.tf32.tf32.f32 "
                 "{%0,%1,%2,%3}, {%4,%5,%6,%7}, {%8,%9}, {%0,%1,%2,%3};"
                 : "+f"(c0), "+f"(c1), "+f"(c2), "+f"(c3)
                 : "r"(a0), "r"(a1), "r"(a2), "r"(a3), "r"(b0), "r"(b1));
}

// ---------------- utility: vectorized copy ---------------------------------
__global__ void copy4_kernel(const float4* __restrict__ in, float4* __restrict__ out, int n4) {
    int i = blockIdx.x * blockDim.x + threadIdx.x;
    if (i < n4) out[i] = in[i];
}

// ---------------- LayerNorm -------------------------------------------------
__global__ void ln_kernel(const float* __restrict__ x,
                          const float* __restrict__ w,
                          const float* __restrict__ b,
                          float* __restrict__ out) {
    int row = blockIdx.x;
    const float* xr = x + (size_t)row * Dd;
    float v[3];
    float lsum = 0.f, lsq = 0.f;
#pragma unroll
    for (int i = 0; i < 3; i++) {
        v[i] = xr[threadIdx.x + i * 256];
        lsum += v[i];
        lsq  += v[i] * v[i];
    }
    __shared__ float s1[256], s2[256];
    s1[threadIdx.x] = lsum; s2[threadIdx.x] = lsq;
    __syncthreads();
    for (int off = 128; off > 0; off >>= 1) {
        if (threadIdx.x < off) {
            s1[threadIdx.x] += s1[threadIdx.x + off];
            s2[threadIdx.x] += s2[threadIdx.x + off];
        }
        __syncthreads();
    }
    float mean = s1[0] * (1.f / 768.f);
    float var  = s2[0] * (1.f / 768.f) - mean * mean;
    float inv  = rsqrtf(var + 1e-5f);
#pragma unroll
    for (int i = 0; i < 3; i++) {
        int c = threadIdx.x + i * 256;
        out[(size_t)row * Dd + c] = (v[i] - mean) * inv * w[c] + b[c];
    }
}

// ---------------- TF32 GEMM with double-buffered smem + register prefetch ----
// BM=128, BN=128, BK=16, 256 threads = 8 warps (2x4), warp tile 64x32.
template<bool GELU, bool RES>
__global__ __launch_bounds__(256) void gemm_tf32(int M, int N, int K,
                               const float* __restrict__ A,
                               const float* __restrict__ Bm,
                               const float* __restrict__ bias,
                               const float* __restrict__ res,
                               float* __restrict__ C) {
    __shared__ uint32_t As[2][16][136];
    __shared__ uint32_t Bs[2][16][136];
    int tid  = threadIdx.x;
    int lane = tid & 31, wid = tid >> 5;
    int wm = (wid >> 2) * 64;
    int wn = (wid & 3) * 32;
    int qr = lane >> 2, qc = lane & 3;
    int row0 = blockIdx.y * 128, col0 = blockIdx.x * 128;

    // per-thread load coordinates
    int aIdx0 = tid * 2, aM0 = aIdx0 >> 2, aK0 = (aIdx0 & 3) * 4;
    int aIdx1 = tid * 2 + 1, aM1 = aIdx1 >> 2, aK1 = (aIdx1 & 3) * 4;
    int bK0 = (tid * 2) >> 5, bN0 = ((tid * 2) & 31) * 4;
    int bK1 = (tid * 2 + 1) >> 5, bN1 = ((tid * 2 + 1) & 31) * 4;

    float acc[4][4][4] = {};
    float4 ap[2], bp[2];

    const int nT = K / 16;
    // prologue: load tile 0 and store into buffer 0
    ap[0] = *(const float4*)(A + (size_t)(row0 + aM0) * K + aK0);
    ap[1] = *(const float4*)(A + (size_t)(row0 + aM1) * K + aK1);
    bp[0] = *(const float4*)(Bm + (size_t)bK0 * N + col0 + bN0);
    bp[1] = *(const float4*)(Bm + (size_t)bK1 * N + col0 + bN1);
    {
        As[0][aK0 + 0][aM0] = f2tf(ap[0].x);
        As[0][aK0 + 1][aM0] = f2tf(ap[0].y);
        As[0][aK0 + 2][aM0] = f2tf(ap[0].z);
        As[0][aK0 + 3][aM0] = f2tf(ap[0].w);
        As[0][aK1 + 0][aM1] = f2tf(ap[1].x);
        As[0][aK1 + 1][aM1] = f2tf(ap[1].y);
        As[0][aK1 + 2][aM1] = f2tf(ap[1].z);
        As[0][aK1 + 3][aM1] = f2tf(ap[1].w);
        uint4 t0, t1;
        t0.x = f2tf(bp[0].x); t0.y = f2tf(bp[0].y); t0.z = f2tf(bp[0].z); t0.w = f2tf(bp[0].w);
        t1.x = f2tf(bp[1].x); t1.y = f2tf(bp[1].y); t1.z = f2tf(bp[1].z); t1.w = f2tf(bp[1].w);
        *(uint4*)&Bs[0][bK0][bN0] = t0;
        *(uint4*)&Bs[0][bK1][bN1] = t1;
    }
    __syncthreads();

    for (int t = 0; t < nT; t++) {
        int cur = t & 1, nxt = cur ^ 1;
        bool more = (t + 1 < nT);
        if (more) {
            int k0 = (t + 1) * 16;
            ap[0] = *(const float4*)(A + (size_t)(row0 + aM0) * K + k0 + aK0);
            ap[1] = *(const float4*)(A + (size_t)(row0 + aM1) * K + k0 + aK1);
            bp[0] = *(const float4*)(Bm + (size_t)(k0 + bK0) * N + col0 + bN0);
            bp[1] = *(const float4*)(Bm + (size_t)(k0 + bK1) * N + col0 + bN1);
        }
#pragma unroll
        for (int ks = 0; ks < 16; ks += 8) {
            uint32_t af[4][4], bf[4][2];
#pragma unroll
            for (int i = 0; i < 4; i++) {
                int m = wm + i * 16 + qr;
                af[i][0] = As[cur][ks + qc][m];
                af[i][1] = As[cur][ks + qc][m + 8];
                af[i][2] = As[cur][ks + qc + 4][m];
                af[i][3] = As[cur][ks + qc + 4][m + 8];
            }
#pragma unroll
            for (int j = 0; j < 4; j++) {
                int n = wn + j * 8 + qr;
                bf[j][0] = Bs[cur][ks + qc][n];
                bf[j][1] = Bs[cur][ks + qc + 4][n];
            }
#pragma unroll
            for (int i = 0; i < 4; i++)
#pragma unroll
                for (int j = 0; j < 4; j++)
                    mma_tf32(acc[i][j][0], acc[i][j][1], acc[i][j][2], acc[i][j][3],
                             af[i][0], af[i][1], af[i][2], af[i][3],
                             bf[j][0], bf[j][1]);
        }
        if (more) {
            As[nxt][aK0 + 0][aM0] = f2tf(ap[0].x);
            As[nxt][aK0 + 1][aM0] = f2tf(ap[0].y);
            As[nxt][aK0 + 2][aM0] = f2tf(ap[0].z);
            As[nxt][aK0 + 3][aM0] = f2tf(ap[0].w);
            As[nxt][aK1 + 0][aM1] = f2tf(ap[1].x);
            As[nxt][aK1 + 1][aM1] = f2tf(ap[1].y);
            As[nxt][aK1 + 2][aM1] = f2tf(ap[1].z);
            As[nxt][aK1 + 3][aM1] = f2tf(ap[1].w);
            uint4 t0, t1;
            t0.x = f2tf(bp[0].x); t0.y = f2tf(bp[0].y); t0.z = f2tf(bp[0].z); t0.w = f2tf(bp[0].w);
            t1.x = f2tf(bp[1].x); t1.y = f2tf(bp[1].y); t1.z = f2tf(bp[1].z); t1.w = f2tf(bp[1].w);
            *(uint4*)&Bs[nxt][bK0][bN0] = t0;
            *(uint4*)&Bs[nxt][bK1][bN1] = t1;
        }
        __syncthreads();
    }
#pragma unroll
    for (int i = 0; i < 4; i++) {
        int r0 = row0 + wm + i * 16 + qr;
        int r1 = r0 + 8;
#pragma unroll
        for (int j = 0; j < 4; j++) {
            int c0 = col0 + wn + j * 8 + qc * 2;
            float v0 = acc[i][j][0] + bias[c0];
            float v1 = acc[i][j][1] + bias[c0 + 1];
            float v2 = acc[i][j][2] + bias[c0];
            float v3 = acc[i][j][3] + bias[c0 + 1];
            if (GELU) {
                v0 = 0.5f * v0 * (1.0f + erff(v0 * 0.70710678f));
                v1 = 0.5f * v1 * (1.0f + erff(v1 * 0.70710678f));
                v2 = 0.5f * v2 * (1.0f + erff(v2 * 0.70710678f));
                v3 = 0.5f * v3 * (1.0f + erff(v3 * 0.70710678f));
            }
            if (RES) {
                float2 r0v = *(const float2*)(res + (size_t)r0 * N + c0);
                float2 r1v = *(const float2*)(res + (size_t)r1 * N + c0);
                v0 += r0v.x; v1 += r0v.y; v2 += r1v.x; v3 += r1v.y;
            }
            *(float2*)(C + (size_t)r0 * N + c0) = make_float2(v0, v1);
            *(float2*)(C + (size_t)r1 * N + c0) = make_float2(v2, v3);
        }
    }
}

// ---------------- fused flash attention (tf32 mma, online softmax) -----------
// grid (16 q-tiles, 24 bh), 256 threads = 8 warps; each warp owns 16 q-rows.
// KV tile = 64 rows. Ks stride 68 (conflict-free S-phase), Vs stride 72
// (conflict-free PV-phase). P panes per warp [16][68]. 2 CTAs/SM.
#define TSV  64
#define KST  68
#define VST  72
#define PST  68
#define FLASH_SMEM ((TSV*KST + TSV*VST + 8*16*PST) * 4)

__global__ __launch_bounds__(256, 2) void flash_tf32(const float* __restrict__ qkv,
                                                     float* __restrict__ vals) {
    extern __shared__ uint32_t sm[];
    uint32_t* Ks   = sm;
    uint32_t* Vs   = sm + TSV * KST;
    uint32_t* Pall = sm + TSV * KST + TSV * VST;

    int tid = threadIdx.x, lane = tid & 31, wid = tid >> 5;
    int qr = lane >> 2, qc = lane & 3;
    int z = blockIdx.y, b = z / Hh, h = z - b * Hh;
    const float* Qb = qkv + (size_t)b * Ss * D3 + h * 192;
    const float* Kb = Qb + 64;
    const float* Vb = Qb + 128;
    int row0 = blockIdx.x * 128;
    uint32_t* Pw = Pall + wid * 16 * PST;
    int wrow = wid * 16;

    // ---- stage Q (pre-scaled, tf32) via Pall scratch, then lift to fragments
    for (int i = tid; i < 2048; i += 256) {
        int t = i >> 4, d = (i & 15) << 2;
        float4 q4 = *(const float4*)(Qb + (size_t)(row0 + t) * D3 + d);
        uint32_t* dst = Pall + t * PST + d;
        dst[0] = f2tf(q4.x * 0.125f);
        dst[1] = f2tf(q4.y * 0.125f);
        dst[2] = f2tf(q4.z * 0.125f);
        dst[3] = f2tf(q4.w * 0.125f);
    }
    __syncthreads();
    uint32_t qa[8][4];
#pragma unroll
    for (int kc = 0; kc < 8; kc++) {
        qa[kc][0] = Pall[(wrow + qr)     * PST + kc * 8 + qc];
        qa[kc][1] = Pall[(wrow + qr + 8) * PST + kc * 8 + qc];
        qa[kc][2] = Pall[(wrow + qr)     * PST + kc * 8 + qc + 4];
        qa[kc][3] = Pall[(wrow + qr + 8) * PST + kc * 8 + qc + 4];
    }
    __syncthreads();

    float m0 = -1e30f, m1 = -1e30f, l0 = 0.f, l1 = 0.f;
    float o[8][4] = {};

    for (int kv = 0; kv < Ss; kv += TSV) {
        // load K/V tiles (tf32-converted once here)
        for (int i = tid; i < 1024; i += 256) {
            int t = i >> 4, d = (i & 15) << 2;
            float4 k4 = *(const float4*)(Kb + (size_t)(kv + t) * D3 + d);
            float4 v4 = *(const float4*)(Vb + (size_t)(kv + t) * D3 + d);
            uint32_t* kd = Ks + t * KST + d;
            kd[0] = f2tf(k4.x); kd[1] = f2tf(k4.y); kd[2] = f2tf(k4.z); kd[3] = f2tf(k4.w);
            uint4 vu;
            vu.x = f2tf(v4.x); vu.y = f2tf(v4.y); vu.z = f2tf(v4.z); vu.w = f2tf(v4.w);
            *(uint4*)(Vs + t * VST + d) = vu;
        }
        __syncthreads();

        // ---- S = Qs @ K^T : 8 n-tiles of 8 cols
        float s[8][4];
#pragma unroll
        for (int j = 0; j < 8; j++) {
            s[j][0] = s[j][1] = s[j][2] = s[j][3] = 0.f;
#pragma unroll
            for (int kc = 0; kc < 8; kc++) {
                uint32_t b0 = Ks[(j * 8 + qr) * KST + kc * 8 + qc];
                uint32_t b1 = Ks[(j * 8 + qr) * KST + kc * 8 + qc + 4];
                mma_tf32(s[j][0], s[j][1], s[j][2], s[j][3],
                         qa[kc][0], qa[kc][1], qa[kc][2], qa[kc][3], b0, b1);
            }
        }

        // ---- online softmax
        float tm0 = -1e30f, tm1 = -1e30f;
#pragma unroll
        for (int j = 0; j < 8; j++) {
            tm0 = fmaxf(tm0, fmaxf(s[j][0], s[j][1]));
            tm1 = fmaxf(tm1, fmaxf(s[j][2], s[j][3]));
        }
        tm0 = fmaxf(tm0, __shfl_xor_sync(0xffffffffu, tm0, 1));
        tm0 = fmaxf(tm0, __shfl_xor_sync(0xffffffffu, tm0, 2));
        tm1 = fmaxf(tm1, __shfl_xor_sync(0xffffffffu, tm1, 1));
        tm1 = fmaxf(tm1, __shfl_xor_sync(0xffffffffu, tm1, 2));
        float mn0 = fmaxf(m0, tm0), mn1 = fmaxf(m1, tm1);
        float sc0 = __expf(m0 - mn0), sc1 = __expf(m1 - mn1);
        m0 = mn0; m1 = mn1;

        float ls0 = 0.f, ls1 = 0.f;
#pragma unroll
        for (int j = 0; j < 8; j++) {
            float p0 = __expf(s[j][0] - m0);
            float p1 = __expf(s[j][1] - m0);
            float p2 = __expf(s[j][2] - m1);
            float p3 = __expf(s[j][3] - m1);
            ls0 += p0 + p1; ls1 += p2 + p3;
            uint2 u0; u0.x = f2tf(p0); u0.y = f2tf(p1);
            uint2 u1; u1.x = f2tf(p2); u1.y = f2tf(p3);
            *(uint2*)(Pw + qr * PST + j * 8 + qc * 2)       = u0;
            *(uint2*)(Pw + (qr + 8) * PST + j * 8 + qc * 2) = u1;
        }
        ls0 += __shfl_xor_sync(0xffffffffu, ls0, 1);
        ls0 += __shfl_xor_sync(0xffffffffu, ls0, 2);
        ls1 += __shfl_xor_sync(0xffffffffu, ls1, 1);
        ls1 += __shfl_xor_sync(0xffffffffu, ls1, 2);
        l0 = l0 * sc0 + ls0;
        l1 = l1 * sc1 + ls1;
#pragma unroll
        for (int j = 0; j < 8; j++) {
            o[j][0] *= sc0; o[j][1] *= sc0; o[j][2] *= sc1; o[j][3] *= sc1;
        }
        __syncwarp();

        // ---- O += P @ V
#pragma unroll
        for (int kc = 0; kc < 8; kc++) {
            uint32_t a0 = Pw[qr * PST + kc * 8 + qc];
            uint32_t a1 = Pw[(qr + 8) * PST + kc * 8 + qc];
            uint32_t a2 = Pw[qr * PST + kc * 8 + qc + 4];
            uint32_t a3 = Pw[(qr + 8) * PST + kc * 8 + qc + 4];
#pragma unroll
            for (int j = 0; j < 8; j++) {
                uint32_t b0 = Vs[(kc * 8 + qc) * VST + j * 8 + qr];
                uint32_t b1 = Vs[(kc * 8 + qc + 4) * VST + j * 8 + qr];
                mma_tf32(o[j][0], o[j][1], o[j][2], o[j][3], a0, a1, a2, a3, b0, b1);
            }
        }
        __syncthreads();
    }

    // ---- epilogue: normalize by l and write out
    float inv0 = 1.f / l0, inv1 = 1.f / l1;
    size_t r0 = (size_t)b * Ss + row0 + wrow + qr;
    size_t r1 = r0 + 8;
#pragma unroll
    for (int j = 0; j < 8; j++) {
        int c0 = h * 64 + j * 8 + qc * 2;
        *(float2*)(vals + r0 * Dd + c0) = make_float2(o[j][0] * inv0, o[j][1] * inv0);
        *(float2*)(vals + r1 * Dd + c0) = make_float2(o[j][2] * inv1, o[j][3] * inv1);
    }
}

// ---------------- host launch ----------------------------------------------
extern "C" void kernel_launch(void* const* d_in, const int* in_sizes, int n_in,
                              void* d_out, int out_size) {
    const float* x     = (const float*)d_in[0];
    const float* qkv_w = (const float*)d_in[1];
    const float* qkv_b = (const float*)d_in[2];
    const float* out_w = (const float*)d_in[3];
    const float* out_b = (const float*)d_in[4];
    const float* ln1_w = (const float*)d_in[5];
    const float* ln1_b = (const float*)d_in[6];
    const float* fc1_w = (const float*)d_in[7];
    const float* fc1_b = (const float*)d_in[8];
    const float* fc2_w = (const float*)d_in[9];
    const float* fc2_b = (const float*)d_in[10];
    const float* ln2_w = (const float*)d_in[11];
    const float* ln2_b = (const float*)d_in[12];

    float *xb, *hb, *qkvb, *vb, *fb;
    cudaGetSymbolAddress((void**)&xb,  g_x);
    cudaGetSymbolAddress((void**)&hb,  g_h);
    cudaGetSymbolAddress((void**)&qkvb,g_qkv);
    cudaGetSymbolAddress((void**)&vb,  g_vals);
    cudaGetSymbolAddress((void**)&fb,  g_ffn);

    cudaFuncSetAttribute(flash_tf32, cudaFuncAttributeMaxDynamicSharedMemorySize, FLASH_SMEM);

    const int nElem = MTOK * Dd;
    const int n4 = nElem / 4;

    copy4_kernel<<<(n4 + 255) / 256, 256>>>((const float4*)x, (float4*)xb, n4);

    for (int l = 0; l < Ll; l++) {
        const float* qw  = qkv_w + (size_t)l * Dd * D3;
        const float* qbb = qkv_b + (size_t)l * D3;
        const float* ow  = out_w + (size_t)l * Dd * Dd;
        const float* ob  = out_b + (size_t)l * Dd;
        const float* l1w = ln1_w + (size_t)l * Dd;
        const float* l1b = ln1_b + (size_t)l * Dd;
        const float* f1w = fc1_w + (size_t)l * Dd * Ii;
        const float* f1b = fc1_b + (size_t)l * Ii;
        const float* f2w = fc2_w + (size_t)l * Ii * Dd;
        const float* f2b = fc2_b + (size_t)l * Dd;
        const float* l2w = ln2_w + (size_t)l * Dd;
        const float* l2b = ln2_b + (size_t)l * Dd;

        ln_kernel<<<MTOK, 256>>>(xb, l1w, l1b, hb);
        gemm_tf32<false, false><<<dim3(D3 / 128, MTOK / 128), 256>>>(
            MTOK, D3, Dd, hb, qw, qbb, nullptr, qkvb);
        flash_tf32<<<dim3(Ss / 128, Bb * Hh), 256, FLASH_SMEM>>>(qkvb, vb);
        gemm_tf32<false, true><<<dim3(Dd / 128, MTOK / 128), 256>>>(
            MTOK, Dd, Dd, vb, ow, ob, xb, xb);
        ln_kernel<<<MTOK, 256>>>(xb, l2w, l2b, hb);
        gemm_tf32<true, false><<<dim3(Ii / 128, MTOK / 128), 256>>>(
            MTOK, Ii, Dd, hb, f1w, f1b, nullptr, fb);
        gemm_tf32<false, true><<<dim3(Dd / 128, MTOK / 128), 256>>>(
            MTOK, Dd, Ii, fb, f2w, f2b, xb, xb);
    }

    copy4_kernel<<<(n4 + 255) / 256, 256>>>((const float4*)xb, (float4*)d_out, n4);
}

// round 5
// speedup vs baseline: 2.9854x; 1.0127x over previous
#include <cuda_runtime.h>
#include <math.h>
#include <stdint.h>

// Problem constants
#define Bb   2
#define Ss   2048
#define Dd   768
#define Hh   12
#define Ii   3072
#define Ll   4
#define HDm  64
#define MTOK (Bb*Ss)          // 4096 tokens
#define D3   (3*Dd)           // 2304

// ---------------- scratch buffers (device globals; no allocation) -----------
__device__ float g_x   [MTOK*Dd];
__device__ float g_h   [MTOK*Dd];
__device__ float g_qkv [MTOK*D3];
__device__ float g_vals[MTOK*Dd];
__device__ float g_ffn [MTOK*Ii];

// ---------------- tf32 helpers ----------------------------------------------
__device__ __forceinline__ uint32_t f2tf(float x) {
    uint32_t r; asm("cvt.rna.tf32.f32 %0, %1;" : "=r"(r) : "f"(x)); return r;
}
__device__ __forceinline__ void mma_tf32(float& c0, float& c1, float& c2, float& c3,
                                         uint32_t a0, uint32_t a1, uint32_t a2, uint32_t a3,
                                         uint32_t b0, uint32_t b1) {
    asm volatile("mma.sync.aligned.m16n8k8.row.col.f32.tf32.tf32.f32 "
                 "{%0,%1,%2,%3}, {%4,%5,%6,%7}, {%8,%9}, {%0,%1,%2,%3};"
                 : "+f"(c0), "+f"(c1), "+f"(c2), "+f"(c3)
                 : "r"(a0), "r"(a1), "r"(a2), "r"(a3), "r"(b0), "r"(b1));
}

// ---------------- LayerNorm -------------------------------------------------
__global__ void ln_kernel(const float* __restrict__ x,
                          const float* __restrict__ w,
                          const float* __restrict__ b,
                          float* __restrict__ out) {
    int row = blockIdx.x;
    const float* xr = x + (size_t)row * Dd;
    float v[3];
    float lsum = 0.f, lsq = 0.f;
#pragma unroll
    for (int i = 0; i < 3; i++) {
        v[i] = xr[threadIdx.x + i * 256];
        lsum += v[i];
        lsq  += v[i] * v[i];
    }
    __shared__ float s1[256], s2[256];
    s1[threadIdx.x] = lsum; s2[threadIdx.x] = lsq;
    __syncthreads();
    for (int off = 128; off > 0; off >>= 1) {
        if (threadIdx.x < off) {
            s1[threadIdx.x] += s1[threadIdx.x + off];
            s2[threadIdx.x] += s2[threadIdx.x + off];
        }
        __syncthreads();
    }
    float mean = s1[0] * (1.f / 768.f);
    float var  = s2[0] * (1.f / 768.f) - mean * mean;
    float inv  = rsqrtf(var + 1e-5f);
#pragma unroll
    for (int i = 0; i < 3; i++) {
        int c = threadIdx.x + i * 256;
        out[(size_t)row * Dd + c] = (v[i] - mean) * inv * w[c] + b[c];
    }
}

// ---------------- TF32 GEMM: double-buffered, 2 CTAs/SM ----------------------
// BM=128, BN=128, BK=16, 256 threads = 8 warps (2x4), warp tile 64x32.
template<bool GELU, bool RES>
__global__ __launch_bounds__(256, 2) void gemm_tf32(int M, int N, int K,
                               const float* __restrict__ A,
                               const float* __restrict__ Bm,
                               const float* __restrict__ bias,
                               const float* __restrict__ res,
                               float* __restrict__ C) {
    __shared__ uint32_t As[2][16][136];
    __shared__ uint32_t Bs[2][16][136];
    int tid  = threadIdx.x;
    int lane = tid & 31, wid = tid >> 5;
    int wm = (wid >> 2) * 64;
    int wn = (wid & 3) * 32;
    int qr = lane >> 2, qc = lane & 3;
    int row0 = blockIdx.y * 128, col0 = blockIdx.x * 128;

    int aIdx0 = tid * 2, aM0 = aIdx0 >> 2, aK0 = (aIdx0 & 3) * 4;
    int aIdx1 = tid * 2 + 1, aM1 = aIdx1 >> 2, aK1 = (aIdx1 & 3) * 4;
    int bK0 = (tid * 2) >> 5, bN0 = ((tid * 2) & 31) * 4;
    int bK1 = (tid * 2 + 1) >> 5, bN1 = ((tid * 2 + 1) & 31) * 4;

    float acc[4][4][4] = {};
    float4 ap[2], bp[2];

    const int nT = K / 16;
    ap[0] = *(const float4*)(A + (size_t)(row0 + aM0) * K + aK0);
    ap[1] = *(const float4*)(A + (size_t)(row0 + aM1) * K + aK1);
    bp[0] = *(const float4*)(Bm + (size_t)bK0 * N + col0 + bN0);
    bp[1] = *(const float4*)(Bm + (size_t)bK1 * N + col0 + bN1);
    {
        As[0][aK0 + 0][aM0] = f2tf(ap[0].x);
        As[0][aK0 + 1][aM0] = f2tf(ap[0].y);
        As[0][aK0 + 2][aM0] = f2tf(ap[0].z);
        As[0][aK0 + 3][aM0] = f2tf(ap[0].w);
        As[0][aK1 + 0][aM1] = f2tf(ap[1].x);
        As[0][aK1 + 1][aM1] = f2tf(ap[1].y);
        As[0][aK1 + 2][aM1] = f2tf(ap[1].z);
        As[0][aK1 + 3][aM1] = f2tf(ap[1].w);
        uint4 t0, t1;
        t0.x = f2tf(bp[0].x); t0.y = f2tf(bp[0].y); t0.z = f2tf(bp[0].z); t0.w = f2tf(bp[0].w);
        t1.x = f2tf(bp[1].x); t1.y = f2tf(bp[1].y); t1.z = f2tf(bp[1].z); t1.w = f2tf(bp[1].w);
        *(uint4*)&Bs[0][bK0][bN0] = t0;
        *(uint4*)&Bs[0][bK1][bN1] = t1;
    }
    __syncthreads();

    for (int t = 0; t < nT; t++) {
        int cur = t & 1, nxt = cur ^ 1;
        bool more = (t + 1 < nT);
        if (more) {
            int k0 = (t + 1) * 16;
            ap[0] = *(const float4*)(A + (size_t)(row0 + aM0) * K + k0 + aK0);
            ap[1] = *(const float4*)(A + (size_t)(row0 + aM1) * K + k0 + aK1);
            bp[0] = *(const float4*)(Bm + (size_t)(k0 + bK0) * N + col0 + bN0);
            bp[1] = *(const float4*)(Bm + (size_t)(k0 + bK1) * N + col0 + bN1);
        }
#pragma unroll
        for (int ks = 0; ks < 16; ks += 8) {
            uint32_t af[4][4], bf[4][2];
#pragma unroll
            for (int i = 0; i < 4; i++) {
                int m = wm + i * 16 + qr;
                af[i][0] = As[cur][ks + qc][m];
                af[i][1] = As[cur][ks + qc][m + 8];
                af[i][2] = As[cur][ks + qc + 4][m];
                af[i][3] = As[cur][ks + qc + 4][m + 8];
            }
#pragma unroll
            for (int j = 0; j < 4; j++) {
                int n = wn + j * 8 + qr;
                bf[j][0] = Bs[cur][ks + qc][n];
                bf[j][1] = Bs[cur][ks + qc + 4][n];
            }
#pragma unroll
            for (int i = 0; i < 4; i++)
#pragma unroll
                for (int j = 0; j < 4; j++)
                    mma_tf32(acc[i][j][0], acc[i][j][1], acc[i][j][2], acc[i][j][3],
                             af[i][0], af[i][1], af[i][2], af[i][3],
                             bf[j][0], bf[j][1]);
        }
        if (more) {
            As[nxt][aK0 + 0][aM0] = f2tf(ap[0].x);
            As[nxt][aK0 + 1][aM0] = f2tf(ap[0].y);
            As[nxt][aK0 + 2][aM0] = f2tf(ap[0].z);
            As[nxt][aK0 + 3][aM0] = f2tf(ap[0].w);
            As[nxt][aK1 + 0][aM1] = f2tf(ap[1].x);
            As[nxt][aK1 + 1][aM1] = f2tf(ap[1].y);
            As[nxt][aK1 + 2][aM1] = f2tf(ap[1].z);
            As[nxt][aK1 + 3][aM1] = f2tf(ap[1].w);
            uint4 t0, t1;
            t0.x = f2tf(bp[0].x); t0.y = f2tf(bp[0].y); t0.z = f2tf(bp[0].z); t0.w = f2tf(bp[0].w);
            t1.x = f2tf(bp[1].x); t1.y = f2tf(bp[1].y); t1.z = f2tf(bp[1].z); t1.w = f2tf(bp[1].w);
            *(uint4*)&Bs[nxt][bK0][bN0] = t0;
            *(uint4*)&Bs[nxt][bK1][bN1] = t1;
        }
        __syncthreads();
    }
#pragma unroll
    for (int i = 0; i < 4; i++) {
        int r0 = row0 + wm + i * 16 + qr;
        int r1 = r0 + 8;
#pragma unroll
        for (int j = 0; j < 4; j++) {
            int c0 = col0 + wn + j * 8 + qc * 2;
            float v0 = acc[i][j][0] + bias[c0];
            float v1 = acc[i][j][1] + bias[c0 + 1];
            float v2 = acc[i][j][2] + bias[c0];
            float v3 = acc[i][j][3] + bias[c0 + 1];
            if (GELU) {
                v0 = 0.5f * v0 * (1.0f + erff(v0 * 0.70710678f));
                v1 = 0.5f * v1 * (1.0f + erff(v1 * 0.70710678f));
                v2 = 0.5f * v2 * (1.0f + erff(v2 * 0.70710678f));
                v3 = 0.5f * v3 * (1.0f + erff(v3 * 0.70710678f));
            }
            if (RES) {
                float2 r0v = *(const float2*)(res + (size_t)r0 * N + c0);
                float2 r1v = *(const float2*)(res + (size_t)r1 * N + c0);
                v0 += r0v.x; v1 += r0v.y; v2 += r1v.x; v3 += r1v.y;
            }
            *(float2*)(C + (size_t)r0 * N + c0) = make_float2(v0, v1);
            *(float2*)(C + (size_t)r1 * N + c0) = make_float2(v2, v3);
        }
    }
}

// ---------------- fused flash attention (unchanged from R4) ------------------
#define TSV  64
#define KST  68
#define VST  72
#define PST  68
#define FLASH_SMEM ((TSV*KST + TSV*VST + 8*16*PST) * 4)

__global__ __launch_bounds__(256, 2) void flash_tf32(const float* __restrict__ qkv,
                                                     float* __restrict__ vals) {
    extern __shared__ uint32_t sm[];
    uint32_t* Ks   = sm;
    uint32_t* Vs   = sm + TSV * KST;
    uint32_t* Pall = sm + TSV * KST + TSV * VST;

    int tid = threadIdx.x, lane = tid & 31, wid = tid >> 5;
    int qr = lane >> 2, qc = lane & 3;
    int z = blockIdx.y, b = z / Hh, h = z - b * Hh;
    const float* Qb = qkv + (size_t)b * Ss * D3 + h * 192;
    const float* Kb = Qb + 64;
    const float* Vb = Qb + 128;
    int row0 = blockIdx.x * 128;
    uint32_t* Pw = Pall + wid * 16 * PST;
    int wrow = wid * 16;

    for (int i = tid; i < 2048; i += 256) {
        int t = i >> 4, d = (i & 15) << 2;
        float4 q4 = *(const float4*)(Qb + (size_t)(row0 + t) * D3 + d);
        uint32_t* dst = Pall + t * PST + d;
        dst[0] = f2tf(q4.x * 0.125f);
        dst[1] = f2tf(q4.y * 0.125f);
        dst[2] = f2tf(q4.z * 0.125f);
        dst[3] = f2tf(q4.w * 0.125f);
    }
    __syncthreads();
    uint32_t qa[8][4];
#pragma unroll
    for (int kc = 0; kc < 8; kc++) {
        qa[kc][0] = Pall[(wrow + qr)     * PST + kc * 8 + qc];
        qa[kc][1] = Pall[(wrow + qr + 8) * PST + kc * 8 + qc];
        qa[kc][2] = Pall[(wrow + qr)     * PST + kc * 8 + qc + 4];
        qa[kc][3] = Pall[(wrow + qr + 8) * PST + kc * 8 + qc + 4];
    }
    __syncthreads();

    float m0 = -1e30f, m1 = -1e30f, l0 = 0.f, l1 = 0.f;
    float o[8][4] = {};

    for (int kv = 0; kv < Ss; kv += TSV) {
        for (int i = tid; i < 1024; i += 256) {
            int t = i >> 4, d = (i & 15) << 2;
            float4 k4 = *(const float4*)(Kb + (size_t)(kv + t) * D3 + d);
            float4 v4 = *(const float4*)(Vb + (size_t)(kv + t) * D3 + d);
            uint32_t* kd = Ks + t * KST + d;
            kd[0] = f2tf(k4.x); kd[1] = f2tf(k4.y); kd[2] = f2tf(k4.z); kd[3] = f2tf(k4.w);
            uint4 vu;
            vu.x = f2tf(v4.x); vu.y = f2tf(v4.y); vu.z = f2tf(v4.z); vu.w = f2tf(v4.w);
            *(uint4*)(Vs + t * VST + d) = vu;
        }
        __syncthreads();

        float s[8][4];
#pragma unroll
        for (int j = 0; j < 8; j++) {
            s[j][0] = s[j][1] = s[j][2] = s[j][3] = 0.f;
#pragma unroll
            for (int kc = 0; kc < 8; kc++) {
                uint32_t b0 = Ks[(j * 8 + qr) * KST + kc * 8 + qc];
                uint32_t b1 = Ks[(j * 8 + qr) * KST + kc * 8 + qc + 4];
                mma_tf32(s[j][0], s[j][1], s[j][2], s[j][3],
                         qa[kc][0], qa[kc][1], qa[kc][2], qa[kc][3], b0, b1);
            }
        }

        float tm0 = -1e30f, tm1 = -1e30f;
#pragma unroll
        for (int j = 0; j < 8; j++) {
            tm0 = fmaxf(tm0, fmaxf(s[j][0], s[j][1]));
            tm1 = fmaxf(tm1, fmaxf(s[j][2], s[j][3]));
        }
        tm0 = fmaxf(tm0, __shfl_xor_sync(0xffffffffu, tm0, 1));
        tm0 = fmaxf(tm0, __shfl_xor_sync(0xffffffffu, tm0, 2));
        tm1 = fmaxf(tm1, __shfl_xor_sync(0xffffffffu, tm1, 1));
        tm1 = fmaxf(tm1, __shfl_xor_sync(0xffffffffu, tm1, 2));
        float mn0 = fmaxf(m0, tm0), mn1 = fmaxf(m1, tm1);
        float sc0 = __expf(m0 - mn0), sc1 = __expf(m1 - mn1);
        m0 = mn0; m1 = mn1;

        float ls0 = 0.f, ls1 = 0.f;
#pragma unroll
        for (int j = 0; j < 8; j++) {
            float p0 = __expf(s[j][0] - m0);
            float p1 = __expf(s[j][1] - m0);
            float p2 = __expf(s[j][2] - m1);
            float p3 = __expf(s[j][3] - m1);
            ls0 += p0 + p1; ls1 += p2 + p3;
            uint2 u0; u0.x = f2tf(p0); u0.y = f2tf(p1);
            uint2 u1; u1.x = f2tf(p2); u1.y = f2tf(p3);
            *(uint2*)(Pw + qr * PST + j * 8 + qc * 2)       = u0;
            *(uint2*)(Pw + (qr + 8) * PST + j * 8 + qc * 2) = u1;
        }
        ls0 += __shfl_xor_sync(0xffffffffu, ls0, 1);
        ls0 += __shfl_xor_sync(0xffffffffu, ls0, 2);
        ls1 += __shfl_xor_sync(0xffffffffu, ls1, 1);
        ls1 += __shfl_xor_sync(0xffffffffu, ls1, 2);
        l0 = l0 * sc0 + ls0;
        l1 = l1 * sc1 + ls1;
#pragma unroll
        for (int j = 0; j < 8; j++) {
            o[j][0] *= sc0; o[j][1] *= sc0; o[j][2] *= sc1; o[j][3] *= sc1;
        }
        __syncwarp();

#pragma unroll
        for (int kc = 0; kc < 8; kc++) {
            uint32_t a0 = Pw[qr * PST + kc * 8 + qc];
            uint32_t a1 = Pw[(qr + 8) * PST + kc * 8 + qc];
            uint32_t a2 = Pw[qr * PST + kc * 8 + qc + 4];
            uint32_t a3 = Pw[(qr + 8) * PST + kc * 8 + qc + 4];
#pragma unroll
            for (int j = 0; j < 8; j++) {
                uint32_t b0 = Vs[(kc * 8 + qc) * VST + j * 8 + qr];
                uint32_t b1 = Vs[(kc * 8 + qc + 4) * VST + j * 8 + qr];
                mma_tf32(o[j][0], o[j][1], o[j][2], o[j][3], a0, a1, a2, a3, b0, b1);
            }
        }
        __syncthreads();
    }

    float inv0 = 1.f / l0, inv1 = 1.f / l1;
    size_t r0 = (size_t)b * Ss + row0 + wrow + qr;
    size_t r1 = r0 + 8;
#pragma unroll
    for (int j = 0; j < 8; j++) {
        int c0 = h * 64 + j * 8 + qc * 2;
        *(float2*)(vals + r0 * Dd + c0) = make_float2(o[j][0] * inv0, o[j][1] * inv0);
        *(float2*)(vals + r1 * Dd + c0) = make_float2(o[j][2] * inv1, o[j][3] * inv1);
    }
}

// ---------------- host launch ----------------------------------------------
extern "C" void kernel_launch(void* const* d_in, const int* in_sizes, int n_in,
                              void* d_out, int out_size) {
    const float* x     = (const float*)d_in[0];
    const float* qkv_w = (const float*)d_in[1];
    const float* qkv_b = (const float*)d_in[2];
    const float* out_w = (const float*)d_in[3];
    const float* out_b = (const float*)d_in[4];
    const float* ln1_w = (const float*)d_in[5];
    const float* ln1_b = (const float*)d_in[6];
    const float* fc1_w = (const float*)d_in[7];
    const float* fc1_b = (const float*)d_in[8];
    const float* fc2_w = (const float*)d_in[9];
    const float* fc2_b = (const float*)d_in[10];
    const float* ln2_w = (const float*)d_in[11];
    const float* ln2_b = (const float*)d_in[12];

    float *xb, *hb, *qkvb, *vb, *fb;
    cudaGetSymbolAddress((void**)&xb,  g_x);
    cudaGetSymbolAddress((void**)&hb,  g_h);
    cudaGetSymbolAddress((void**)&qkvb,g_qkv);
    cudaGetSymbolAddress((void**)&vb,  g_vals);
    cudaGetSymbolAddress((void**)&fb,  g_ffn);

    cudaFuncSetAttribute(flash_tf32, cudaFuncAttributeMaxDynamicSharedMemorySize, FLASH_SMEM);

    for (int l = 0; l < Ll; l++) {
        const float* qw  = qkv_w + (size_t)l * Dd * D3;
        const float* qbb = qkv_b + (size_t)l * D3;
        const float* ow  = out_w + (size_t)l * Dd * Dd;
        const float* ob  = out_b + (size_t)l * Dd;
        const float* l1w = ln1_w + (size_t)l * Dd;
        const float* l1b = ln1_b + (size_t)l * Dd;
        const float* f1w = fc1_w + (size_t)l * Dd * Ii;
        const float* f1b = fc1_b + (size_t)l * Ii;
        const float* f2w = fc2_w + (size_t)l * Ii * Dd;
        const float* f2b = fc2_b + (size_t)l * Dd;
        const float* l2w = ln2_w + (size_t)l * Dd;
        const float* l2b = ln2_b + (size_t)l * Dd;

        const float* xin  = (l == 0) ? x : xb;   // residual stream input
        float* xout_ffn   = (l == Ll - 1) ? (float*)d_out : xb;

        // 1. h = LN1(x)
        ln_kernel<<<MTOK, 256>>>(xin, l1w, l1b, hb);
        // 2. qkv projection
        gemm_tf32<false, false><<<dim3(D3 / 128, MTOK / 128), 256>>>(
            MTOK, D3, Dd, hb, qw, qbb, nullptr, qkvb);
        // 3-5. fused attention
        flash_tf32<<<dim3(Ss / 128, Bb * Hh), 256, FLASH_SMEM>>>(qkvb, vb);
        // 6. x = xin + vals @ out_w + out_b  (writes xb)
        gemm_tf32<false, true><<<dim3(Dd / 128, MTOK / 128), 256>>>(
            MTOK, Dd, Dd, vb, ow, ob, xin, xb);
        // 7. h = LN2(x)
        ln_kernel<<<MTOK, 256>>>(xb, l2w, l2b, hb);
        // 8. ffn = gelu(h @ fc1_w + fc1_b)
        gemm_tf32<true, false><<<dim3(Ii / 128, MTOK / 128), 256>>>(
            MTOK, Ii, Dd, hb, f1w, f1b, nullptr, fb);
        // 9. x = xb + ffn @ fc2_w + fc2_b   (last layer writes d_out directly)
        gemm_tf32<false, true><<<dim3(Dd / 128, MTOK / 128), 256>>>(
            MTOK, Dd, Ii, fb, f2w, f2b, xb, xout_ffn);
    }
}